// round 1
// baseline (speedup 1.0000x reference)
#include <cuda_runtime.h>
#include <cstdint>

// Problem constants
#define Bsz 8
#define Pt 12          // time steps (P == Q == 12)
#define Nn 5000
#define Dm 64
#define NPB 16         // nodes per block (one 16-thread group per node)
#define THREADS 256
#define NODE_STRIDE 776   // 12*64 + 8 pad (8-bank offset between adjacent groups)
#define WT_STRIDE 66      // padded transposed-weight row stride (2-way max conflicts)

typedef unsigned long long u64;

__device__ __forceinline__ u64 fma2(u64 a, u64 b, u64 c) {
    u64 d;
    asm("fma.rn.f32x2 %0, %1, %2, %3;" : "=l"(d) : "l"(a), "l"(b), "l"(c));
    return d;
}
__device__ __forceinline__ u64 dup2(float x) {
    u64 d; unsigned r = __float_as_uint(x);
    asm("mov.b64 %0, {%1, %1};" : "=l"(d) : "r"(r));
    return d;
}
__device__ __forceinline__ u64 pack2(float x, float y) {
    u64 d;
    asm("mov.b64 %0, {%1, %2};" : "=l"(d)
        : "r"(__float_as_uint(x)), "r"(__float_as_uint(y)));
    return d;
}
__device__ __forceinline__ float2 unpack2(u64 v) {
    unsigned lo, hi;
    asm("mov.b64 {%0, %1}, %2;" : "=r"(lo), "=r"(hi) : "l"(v));
    return make_float2(__uint_as_float(lo), __uint_as_float(hi));
}

// Stage one 64x64 weight into smem TRANSPOSED (sWt[i*66 + j] = W[j*64 + i]).
// Global read is coalesced; STS is 2-way-conflicted max thanks to stride 66.
__device__ __forceinline__ void load_weight(const float* __restrict__ Wg,
                                            const float* __restrict__ bg,
                                            float* __restrict__ sWt,
                                            float* __restrict__ sBias,
                                            int tid)
{
#pragma unroll
    for (int r = 0; r < 16; r++) {
        int idx = r * 256 + tid;       // 0..4095
        int j = idx >> 6;
        int i = idx & 63;
        sWt[i * WT_STRIDE + j] = Wg[idx];
    }
    if (tid < 64) sBias[tid] = bg[tid];
}

// 12x64 = [12,64]x[64,64]^T GEMM for one node, done by 16 threads.
// Thread l computes columns j0..j0+3 for all 12 rows, packed f32x2 accumulators.
__device__ __forceinline__ void gemm12x64(const float* __restrict__ xin,   // [12][64] smem
                                          const float* __restrict__ sWt,   // [64][66] transposed
                                          const float* __restrict__ sBias,
                                          float* __restrict__ dst,
                                          int dstride,
                                          int l,
                                          bool relu)
{
    const int j0 = l * 4;
    u64 acc0[12], acc1[12];
    const u64 bi01 = pack2(sBias[j0],     sBias[j0 + 1]);
    const u64 bi23 = pack2(sBias[j0 + 2], sBias[j0 + 3]);
#pragma unroll
    for (int t = 0; t < 12; t++) { acc0[t] = bi01; acc1[t] = bi23; }

#pragma unroll 4
    for (int i = 0; i < 64; i += 2) {
        const float* w = sWt + i * WT_STRIDE + j0;
        const u64 w0a = *(const u64*)(w);
        const u64 w0b = *(const u64*)(w + 2);
        const u64 w1a = *(const u64*)(w + WT_STRIDE);
        const u64 w1b = *(const u64*)(w + WT_STRIDE + 2);
#pragma unroll
        for (int t = 0; t < 12; t++) {
            const float2 x = *(const float2*)(xin + t * 64 + i);
            const u64 xa = dup2(x.x);
            const u64 xb = dup2(x.y);
            acc0[t] = fma2(w0a, xa, acc0[t]);
            acc1[t] = fma2(w0b, xa, acc1[t]);
            acc0[t] = fma2(w1a, xb, acc0[t]);
            acc1[t] = fma2(w1b, xb, acc1[t]);
        }
    }

#pragma unroll
    for (int t = 0; t < 12; t++) {
        const float2 v0 = unpack2(acc0[t]);
        const float2 v1 = unpack2(acc1[t]);
        float4 o = make_float4(v0.x, v0.y, v1.x, v1.y);
        if (relu) {
            o.x = fmaxf(o.x, 0.f); o.y = fmaxf(o.y, 0.f);
            o.z = fmaxf(o.z, 0.f); o.w = fmaxf(o.w, 0.f);
        }
        *(float4*)(dst + t * dstride + j0) = o;
    }
}

__global__ void __launch_bounds__(THREADS)
fused_attn_kernel(const float* __restrict__ X,
                  const float* __restrict__ STE_P,
                  const float* __restrict__ STE_Q,
                  const float* __restrict__ W21, const float* __restrict__ b21,
                  const float* __restrict__ W22, const float* __restrict__ b22,
                  const float* __restrict__ W23, const float* __restrict__ b23,
                  const float* __restrict__ W24, const float* __restrict__ b24,
                  const float* __restrict__ W25, const float* __restrict__ b25,
                  float* __restrict__ Out)
{
    extern __shared__ float smem[];
    float* sWt   = smem;                        // 64*66 = 4224
    float* sBias = sWt + 64 * WT_STRIDE;        // 64
    float* sIN   = sBias + 64;                  // 16 * 776  (also attention output buf)
    float* sQ    = sIN + NPB * NODE_STRIDE;     // also FFN hidden buf
    float* sK    = sQ  + NPB * NODE_STRIDE;
    float* sV    = sK  + NPB * NODE_STRIDE;

    const int tid = threadIdx.x;
    const int g   = tid >> 4;     // group (node within block)
    const int l   = tid & 15;     // lane within group
    const int b   = blockIdx.y;
    const int n   = blockIdx.x * NPB + g;
    const bool valid = (n < Nn);

    float* myIN = sIN + g * NODE_STRIDE;
    float* myQ  = sQ  + g * NODE_STRIDE;
    float* myK  = sK  + g * NODE_STRIDE;
    float* myV  = sV  + g * NODE_STRIDE;

    // global base for this (b, n): elem ((b*12 + t)*5000 + n)*64
    const int gbase = b * (Pt * Nn * Dm) + n * Dm;

    // ---- helper: load 12x64 input rows for this node into myIN ----
    // (inlined as a macro-ish lambda-free block; done per phase)
#define LOAD_INPUT(SRC)                                                     \
    if (valid) {                                                            \
        _Pragma("unroll")                                                   \
        for (int t = 0; t < 12; t++) {                                      \
            const float4 v = *(const float4*)((SRC) + gbase + t * (Nn * Dm) + l * 4); \
            *(float4*)(myIN + t * 64 + l * 4) = v;                          \
        }                                                                   \
    }

    // ---------------- Phase A: q = relu(STE_Q @ W21^T + b21) ----------------
    load_weight(W21, b21, sWt, sBias, tid);
    LOAD_INPUT(STE_Q);
    __syncthreads();
    if (valid) gemm12x64(myIN, sWt, sBias, myQ, 64, l, true);
    __syncthreads();

    // ---------------- Phase B: k = relu(STE_P @ W22^T + b22) ----------------
    load_weight(W22, b22, sWt, sBias, tid);
    LOAD_INPUT(STE_P);
    __syncthreads();
    if (valid) gemm12x64(myIN, sWt, sBias, myK, 64, l, true);
    __syncthreads();

    // ---------------- Phase C: v = relu(X @ W23^T + b23) --------------------
    load_weight(W23, b23, sWt, sBias, tid);
    LOAD_INPUT(X);
    __syncthreads();
    if (valid) gemm12x64(myIN, sWt, sBias, myV, 64, l, true);
    __syncthreads();

    // ---------------- Attention (per node, 8 heads x 12 q; writes myIN) -----
    if (valid) {
        const int h8 = (l & 7) * 8;        // head offset in D
        const int q0 = (l >> 3) * 6;       // this thread handles 6 q values
#pragma unroll
        for (int m = 0; m < 6; m++) {
            const int q = q0 + m;
            float qv[8];
#pragma unroll
            for (int d = 0; d < 8; d++) qv[d] = myQ[q * 64 + h8 + d];

            float s[12];
            float mx = -1e30f;
#pragma unroll
            for (int p = 0; p < 12; p++) {
                float acc = 0.f;
#pragma unroll
                for (int d = 0; d < 8; d++) acc += qv[d] * myK[p * 64 + h8 + d];
                s[p] = acc * 0.35355339059327373f;   // 1/sqrt(8)
                mx = fmaxf(mx, s[p]);
            }
            float sum = 0.f;
#pragma unroll
            for (int p = 0; p < 12; p++) { s[p] = __expf(s[p] - mx); sum += s[p]; }
            const float inv = __fdividef(1.f, sum);

            float o[8];
#pragma unroll
            for (int d = 0; d < 8; d++) o[d] = 0.f;
#pragma unroll
            for (int p = 0; p < 12; p++) {
                const float a = s[p] * inv;
#pragma unroll
                for (int d = 0; d < 8; d++) o[d] += a * myV[p * 64 + h8 + d];
            }
#pragma unroll
            for (int d = 0; d < 8; d++) myIN[q * 64 + h8 + d] = o[d];
        }
    }
    __syncthreads();

    // ---------------- Phase D: h = relu(attn_out @ W24^T + b24) -------------
    load_weight(W24, b24, sWt, sBias, tid);
    __syncthreads();
    if (valid) gemm12x64(myIN, sWt, sBias, myQ, 64, l, true);   // reuse sQ as hidden
    __syncthreads();

    // ---------------- Phase E: out = h @ W25^T + b25  (to global) -----------
    load_weight(W25, b25, sWt, sBias, tid);
    __syncthreads();
    if (valid) gemm12x64(myQ, sWt, sBias, Out + gbase, Nn * Dm, l, false);

#undef LOAD_INPUT
}

extern "C" void kernel_launch(void* const* d_in, const int* in_sizes, int n_in,
                              void* d_out, int out_size)
{
    const float* X     = (const float*)d_in[0];
    const float* STE_P = (const float*)d_in[1];
    const float* STE_Q = (const float*)d_in[2];
    const float* W21   = (const float*)d_in[3];
    const float* b21   = (const float*)d_in[4];
    const float* W22   = (const float*)d_in[5];
    const float* b22   = (const float*)d_in[6];
    const float* W23   = (const float*)d_in[7];
    const float* b23   = (const float*)d_in[8];
    const float* W24   = (const float*)d_in[9];
    const float* b24   = (const float*)d_in[10];
    const float* W25   = (const float*)d_in[11];
    const float* b25   = (const float*)d_in[12];
    float* Out = (float*)d_out;

    const size_t smem_bytes =
        (size_t)(64 * WT_STRIDE + 64 + 4 * NPB * NODE_STRIDE) * sizeof(float); // 215,808 B

    cudaFuncSetAttribute(fused_attn_kernel,
                         cudaFuncAttributeMaxDynamicSharedMemorySize,
                         (int)smem_bytes);

    dim3 grid((Nn + NPB - 1) / NPB, Bsz);   // (313, 8)
    fused_attn_kernel<<<grid, THREADS, smem_bytes>>>(
        X, STE_P, STE_Q,
        W21, b21, W22, b22, W23, b23, W24, b24, W25, b25,
        Out);
}